// round 1
// baseline (speedup 1.0000x reference)
#include <cuda_runtime.h>
#include <cuda_bf16.h>
#include <math.h>

// ---------------- problem constants ----------------
#define CDIM   96
#define DD     32
#define HH     64
#define WWD    64
#define BATCH  2
#define SP     131072              // D*H*W
#define NTOK   (BATCH * SP)        // 262144 tokens
#define NWIN   2048                // windows per batch (8*16*16)
#define NHEAD  4
#define HDIM   24
#define NWT    64                  // tokens per window

// ---------------- device scratch (static; no allocs allowed) ----------------
__device__ float g_xw  [(size_t)NTOK * CDIM];       // LN1'd, rolled, windowed  (win-token-major)
__device__ float g_qkv [(size_t)NTOK * 3 * CDIM];   // qkv                      (win-token-major)
__device__ float g_att [(size_t)NTOK * CDIM];       // attention out            (win-token-major)
__device__ float g_proj[(size_t)NTOK * CDIM];       // proj out                 (win-token-major)
__device__ float g_x2  [(size_t)NTOK * CDIM];       // residual after attn      (spatial token-major)
__device__ float g_hn  [(size_t)NTOK * CDIM];       // LN2 out                  (spatial token-major)
__device__ float g_m1  [(size_t)NTOK * 4 * CDIM];   // fc1+gelu out
__device__ float g_m2  [(size_t)NTOK * CDIM];       // fc2 out

// ============================================================
// K1: LN1 + roll(-2) + window partition.
// Block = (b, d, h, w0..w0+31). Load 96x32 tile (coalesced over w),
// LN per token, scatter rows to windowed layout (96-float contiguous writes).
// ============================================================
__global__ void k_ln1_window(const float* __restrict__ x,
                             const float* __restrict__ gw,
                             const float* __restrict__ gb)
{
    __shared__ float sm[CDIM][33];
    __shared__ float s_mean[32], s_rstd[32];
    __shared__ int   s_row[32];

    int blk = blockIdx.x;
    int wt  = blk & 1;
    int h   = (blk >> 1) & 63;
    int d   = (blk >> 7) & 31;
    int b   = blk >> 12;
    int w0  = wt * 32;
    int tid = threadIdx.x;   // 128

    const float* xb = x + (size_t)b * CDIM * SP + (size_t)d * 4096 + h * 64 + w0;
    for (int i = tid; i < CDIM * 32; i += 128) {
        int c = i >> 5, t = i & 31;
        sm[c][t] = xb[(size_t)c * SP + t];
    }
    __syncthreads();

    if (tid < 32) {
        float s = 0.f, ss = 0.f;
        #pragma unroll
        for (int c = 0; c < CDIM; c++) { float v = sm[c][tid]; s += v; ss += v * v; }
        float mean = s * (1.f / CDIM);
        float var  = ss * (1.f / CDIM) - mean * mean;
        s_mean[tid] = mean;
        s_rstd[tid] = rsqrtf(var + 1e-5f);
        int w  = w0 + tid;
        int ds = (d + DD - 2) & (DD - 1);
        int hs = (h + HH - 2) & (HH - 1);
        int ws = (w + WWD - 2) & (WWD - 1);
        int widx  = ((ds >> 2) * 16 + (hs >> 2)) * 16 + (ws >> 2);
        int inner = ((ds & 3) * 16) + ((hs & 3) * 4) + (ws & 3);
        s_row[tid] = (b * NWIN + widx) * NWT + inner;
    }
    __syncthreads();

    for (int i = tid; i < 32 * CDIM; i += 128) {
        int t = i / CDIM, c = i - t * CDIM;
        float v = (sm[c][t] - s_mean[t]) * s_rstd[t] * gw[c] + gb[c];
        g_xw[(size_t)s_row[t] * CDIM + c] = v;
    }
}

// ============================================================
// GEMM: C[M,Nc] = A[M,K] @ W[Nc,K]^T + bias, optional exact GELU.
// 128x96 block tile, 256 threads, 8x6 per-thread microtile, K-chunks of 16.
// Assumes M%128==0, Nc%96==0, K%16==0 (true for all call sites).
// ============================================================
#define GBM 128
#define GBN 96
#define GBK 16
__global__ void __launch_bounds__(256)
k_gemm(const float* __restrict__ A, const float* __restrict__ Wt,
       const float* __restrict__ bias, float* __restrict__ Cout,
       int K, int Nc, int act)
{
    __shared__ float As[GBK][GBM];
    __shared__ float Bs[GBK][GBN];
    int tid = threadIdx.x;
    int tx  = tid & 15;    // N: 16 * 6 = 96
    int ty  = tid >> 4;    // M: 16 * 8 = 128
    size_t bm = (size_t)blockIdx.y * GBM;
    int    bn = blockIdx.x * GBN;

    float acc[8][6];
    #pragma unroll
    for (int i = 0; i < 8; i++)
        #pragma unroll
        for (int j = 0; j < 6; j++) acc[i][j] = 0.f;

    for (int k0 = 0; k0 < K; k0 += GBK) {
        #pragma unroll
        for (int r = 0; r < 2; r++) {
            int i  = tid + r * 256;
            int m  = i >> 2;
            int k4 = (i & 3) << 2;
            float4 v = *(const float4*)&A[(bm + m) * K + k0 + k4];
            As[k4 + 0][m] = v.x; As[k4 + 1][m] = v.y;
            As[k4 + 2][m] = v.z; As[k4 + 3][m] = v.w;
        }
        for (int i = tid; i < 384; i += 256) {
            int n  = i >> 2;
            int k4 = (i & 3) << 2;
            float4 v = *(const float4*)&Wt[(size_t)(bn + n) * K + k0 + k4];
            Bs[k4 + 0][n] = v.x; Bs[k4 + 1][n] = v.y;
            Bs[k4 + 2][n] = v.z; Bs[k4 + 3][n] = v.w;
        }
        __syncthreads();
        #pragma unroll
        for (int kk = 0; kk < GBK; kk++) {
            float a[8], bb[6];
            #pragma unroll
            for (int i = 0; i < 8; i++) a[i] = As[kk][ty * 8 + i];
            #pragma unroll
            for (int j = 0; j < 6; j++) bb[j] = Bs[kk][tx * 6 + j];
            #pragma unroll
            for (int i = 0; i < 8; i++)
                #pragma unroll
                for (int j = 0; j < 6; j++)
                    acc[i][j] = fmaf(a[i], bb[j], acc[i][j]);
        }
        __syncthreads();
    }

    #pragma unroll
    for (int i = 0; i < 8; i++) {
        size_t row = bm + ty * 8 + i;
        #pragma unroll
        for (int j = 0; j < 6; j++) {
            int n = bn + tx * 6 + j;
            float v = acc[i][j] + bias[n];
            if (act) v = 0.5f * v * (1.f + erff(v * 0.70710678118654752f));
            Cout[row * Nc + n] = v;
        }
    }
}

// ============================================================
// K3: windowed attention. Block = (window bn, head hh), 64 threads,
// one softmax row per thread. Bias + shift-mask computed analytically.
// ============================================================
__global__ void __launch_bounds__(64)
k_attn(const float* __restrict__ rpb)
{
    __shared__ float kk[NWT][HDIM];
    __shared__ float vv[NWT][HDIM];
    __shared__ float bcol[343];
    __shared__ int   gtok[NWT];

    int bn  = blockIdx.x;
    int hh  = blockIdx.y;
    int tid = threadIdx.x;   // 64

    const float* qkvb = g_qkv + (size_t)bn * NWT * (3 * CDIM) + hh * HDIM;
    for (int i = tid; i < NWT * HDIM; i += 64) {
        int j = i / HDIM, dd = i - j * HDIM;
        kk[j][dd] = qkvb[j * (3 * CDIM) +  CDIM      + dd];
        vv[j][dd] = qkvb[j * (3 * CDIM) + (2 * CDIM) + dd];
    }
    for (int i = tid; i < 343; i += 64) bcol[i] = rpb[i * NHEAD + hh];

    int widx = bn & (NWIN - 1);
    int wd = widx >> 8, wh = (widx >> 4) & 15, ww = widx & 15;
    int id = tid >> 4, ih = (tid >> 2) & 3, iw = tid & 3;
    int da = wd * 4 + id, ha = wh * 4 + ih, wa = ww * 4 + iw;
    int rd = (da < DD  - 4) ? 0 : ((da < DD  - 2) ? 1 : 2);
    int rh = (ha < HH  - 4) ? 0 : ((ha < HH  - 2) ? 1 : 2);
    int rw = (wa < WWD - 4) ? 0 : ((wa < WWD - 2) ? 1 : 2);
    gtok[tid] = rd * 9 + rh * 3 + rw;

    float q[HDIM];
    #pragma unroll
    for (int dd = 0; dd < HDIM; dd++)
        q[dd] = qkvb[tid * (3 * CDIM) + dd] * 0.2041241452319315f;  // 24^-0.5
    __syncthreads();

    int mygrp = gtok[tid];
    float s[NWT];
    float mx = -1e30f;
    #pragma unroll
    for (int j = 0; j < NWT; j++) {
        float a = 0.f;
        #pragma unroll
        for (int dd = 0; dd < HDIM; dd++)
            a = fmaf(q[dd], kk[j][dd], a);
        int jd = j >> 4, jh = (j >> 2) & 3, jw = j & 3;
        int rel = (id - jd + 3) * 49 + (ih - jh + 3) * 7 + (iw - jw + 3);
        a += bcol[rel];
        if (gtok[j] != mygrp) a -= 100.f;
        s[j] = a;
        mx = fmaxf(mx, a);
    }
    float sum = 0.f;
    #pragma unroll
    for (int j = 0; j < NWT; j++) { float e = __expf(s[j] - mx); s[j] = e; sum += e; }
    float inv = 1.f / sum;

    float o[HDIM];
    #pragma unroll
    for (int dd = 0; dd < HDIM; dd++) o[dd] = 0.f;
    #pragma unroll
    for (int j = 0; j < NWT; j++) {
        float p = s[j];
        #pragma unroll
        for (int dd = 0; dd < HDIM; dd++)
            o[dd] = fmaf(p, vv[j][dd], o[dd]);
    }
    float* op = g_att + ((size_t)bn * NWT + tid) * CDIM + hh * HDIM;
    #pragma unroll
    for (int dd = 0; dd < HDIM; dd++) op[dd] = o[dd] * inv;
}

// ============================================================
// K4: window reverse + roll(+2) + residual add + LN2.
// Writes g_x2 (residual) and g_hn (LN2 out) in spatial token-major order.
// ============================================================
__global__ void k_res_ln2(const float* __restrict__ x,
                          const float* __restrict__ g2,
                          const float* __restrict__ b2)
{
    __shared__ float sm[CDIM][33];
    __shared__ float s_mean[32], s_rstd[32];
    __shared__ int   s_row[32];

    int blk = blockIdx.x;
    int wt  = blk & 1;
    int h   = (blk >> 1) & 63;
    int d   = (blk >> 7) & 31;
    int b   = blk >> 12;
    int w0  = wt * 32;
    int tid = threadIdx.x;   // 128

    if (tid < 32) {
        int w  = w0 + tid;
        int ds = (d + DD - 2) & (DD - 1);
        int hs = (h + HH - 2) & (HH - 1);
        int ws = (w + WWD - 2) & (WWD - 1);
        int widx  = ((ds >> 2) * 16 + (hs >> 2)) * 16 + (ws >> 2);
        int inner = ((ds & 3) * 16) + ((hs & 3) * 4) + (ws & 3);
        s_row[tid] = (b * NWIN + widx) * NWT + inner;
    }
    const float* xb = x + (size_t)b * CDIM * SP + (size_t)d * 4096 + h * 64 + w0;
    for (int i = tid; i < CDIM * 32; i += 128) {
        int c = i >> 5, t = i & 31;
        sm[c][t] = xb[(size_t)c * SP + t];
    }
    __syncthreads();
    for (int i = tid; i < 32 * CDIM; i += 128) {
        int t = i / CDIM, c = i - t * CDIM;
        sm[c][t] += g_proj[(size_t)s_row[t] * CDIM + c];
    }
    __syncthreads();
    if (tid < 32) {
        float s = 0.f, ss = 0.f;
        #pragma unroll
        for (int c = 0; c < CDIM; c++) { float v = sm[c][tid]; s += v; ss += v * v; }
        float mean = s * (1.f / CDIM);
        s_mean[tid] = mean;
        s_rstd[tid] = rsqrtf(ss * (1.f / CDIM) - mean * mean + 1e-5f);
    }
    __syncthreads();
    size_t tokbase = (size_t)b * SP + (size_t)d * 4096 + h * 64 + w0;
    for (int i = tid; i < 32 * CDIM; i += 128) {
        int t = i / CDIM, c = i - t * CDIM;
        float v = sm[c][t];
        size_t off = (tokbase + t) * CDIM + c;
        g_x2[off] = v;
        g_hn[off] = (v - s_mean[t]) * s_rstd[t] * g2[c] + b2[c];
    }
}

// ============================================================
// K7: final residual + transpose to (B, C, D, H, W)
// ============================================================
__global__ void k_final(float* __restrict__ out)
{
    __shared__ float sm[CDIM][33];
    int blk = blockIdx.x;
    int wt  = blk & 1;
    int h   = (blk >> 1) & 63;
    int d   = (blk >> 7) & 31;
    int b   = blk >> 12;
    int w0  = wt * 32;
    int tid = threadIdx.x;   // 128

    size_t tokbase = (size_t)b * SP + (size_t)d * 4096 + h * 64 + w0;
    for (int i = tid; i < 32 * CDIM; i += 128) {
        int t = i / CDIM, c = i - t * CDIM;
        size_t off = (tokbase + t) * CDIM + c;
        sm[c][t] = g_x2[off] + g_m2[off];
    }
    __syncthreads();
    float* ob = out + (size_t)b * CDIM * SP + (size_t)d * 4096 + h * 64 + w0;
    for (int i = tid; i < CDIM * 32; i += 128) {
        int c = i >> 5, t = i & 31;
        ob[(size_t)c * SP + t] = sm[c][t];
    }
}

// ============================================================
// launch
// ============================================================
extern "C" void kernel_launch(void* const* d_in, const int* in_sizes, int n_in,
                              void* d_out, int out_size)
{
    const float* x    = (const float*)d_in[0];
    const float* n1g  = (const float*)d_in[1];
    const float* n1b  = (const float*)d_in[2];
    const float* qkvw = (const float*)d_in[3];
    const float* qkvb = (const float*)d_in[4];
    const float* rpb  = (const float*)d_in[5];
    const float* pw   = (const float*)d_in[6];
    const float* pb   = (const float*)d_in[7];
    const float* n2g  = (const float*)d_in[8];
    const float* n2b  = (const float*)d_in[9];
    const float* f1w  = (const float*)d_in[10];
    const float* f1b  = (const float*)d_in[11];
    const float* f2w  = (const float*)d_in[12];
    const float* f2b  = (const float*)d_in[13];
    float* out = (float*)d_out;

    float *p_xw, *p_qkv, *p_att, *p_proj, *p_hn, *p_m1, *p_m2;
    cudaGetSymbolAddress((void**)&p_xw,  g_xw);
    cudaGetSymbolAddress((void**)&p_qkv, g_qkv);
    cudaGetSymbolAddress((void**)&p_att, g_att);
    cudaGetSymbolAddress((void**)&p_proj,g_proj);
    cudaGetSymbolAddress((void**)&p_hn,  g_hn);
    cudaGetSymbolAddress((void**)&p_m1,  g_m1);
    cudaGetSymbolAddress((void**)&p_m2,  g_m2);

    const int nblk_sp = BATCH * DD * HH * (WWD / 32);   // 8192

    // 1. LN1 + roll + window partition
    k_ln1_window<<<nblk_sp, 128>>>(x, n1g, n1b);

    // 2. qkv GEMM: (262144 x 96) @ (288 x 96)^T
    k_gemm<<<dim3(3, NTOK / GBM), 256>>>(p_xw, qkvw, qkvb, p_qkv, 96, 288, 0);

    // 3. attention
    k_attn<<<dim3(BATCH * NWIN, NHEAD), 64>>>(rpb);

    // 4. proj GEMM: (262144 x 96) @ (96 x 96)^T
    k_gemm<<<dim3(1, NTOK / GBM), 256>>>(p_att, pw, pb, p_proj, 96, 96, 0);

    // 5. reverse window + roll back + residual + LN2
    k_res_ln2<<<nblk_sp, 128>>>(x, n2g, n2b);

    // 6. fc1 GEMM + GELU: (262144 x 96) @ (384 x 96)^T
    k_gemm<<<dim3(4, NTOK / GBM), 256>>>(p_hn, f1w, f1b, p_m1, 96, 384, 1);

    // 7. fc2 GEMM: (262144 x 384) @ (96 x 384)^T
    k_gemm<<<dim3(1, NTOK / GBM), 256>>>(p_m1, f2w, f2b, p_m2, 384, 96, 0);

    // 8. final residual + transpose to (B, C, D, H, W)
    k_final<<<nblk_sp, 128>>>(out);
}

// round 2
// speedup vs baseline: 1.8008x; 1.8008x over previous
#include <cuda_runtime.h>
#include <cuda_bf16.h>
#include <math.h>
#include <stdint.h>

// ---------------- problem constants ----------------
#define CDIM   96
#define DD     32
#define HH     64
#define WWD    64
#define BATCH  2
#define SP     131072              // D*H*W
#define NTOK   (BATCH * SP)        // 262144 tokens
#define NWIN   2048                // windows per batch (8*16*16)
#define NHEAD  4
#define HDIM   24
#define NWT    64                  // tokens per window

// ---------------- device scratch (static; no allocs allowed) ----------------
__device__ float g_xw  [(size_t)NTOK * CDIM];       // LN1'd, rolled, windowed  (win-token-major)
__device__ float g_qkv [(size_t)NTOK * 3 * CDIM];   // qkv                      (win-token-major)
__device__ float g_att [(size_t)NTOK * CDIM];       // attention out            (win-token-major)
__device__ float g_proj[(size_t)NTOK * CDIM];       // proj out                 (win-token-major)
__device__ float g_x2  [(size_t)NTOK * CDIM];       // residual after attn      (spatial token-major)
__device__ float g_hn  [(size_t)NTOK * CDIM];       // LN2 out                  (spatial token-major)
__device__ float g_m1  [(size_t)NTOK * 4 * CDIM];   // fc1+gelu out
__device__ float g_m2  [(size_t)NTOK * CDIM];       // fc2 out

// ============================================================
// K1: LN1 + roll(-2) + window partition.
// ============================================================
__global__ void k_ln1_window(const float* __restrict__ x,
                             const float* __restrict__ gw,
                             const float* __restrict__ gb)
{
    __shared__ float sm[CDIM][33];
    __shared__ float s_mean[32], s_rstd[32];
    __shared__ int   s_row[32];

    int blk = blockIdx.x;
    int wt  = blk & 1;
    int h   = (blk >> 1) & 63;
    int d   = (blk >> 7) & 31;
    int b   = blk >> 12;
    int w0  = wt * 32;
    int tid = threadIdx.x;   // 128

    const float* xb = x + (size_t)b * CDIM * SP + (size_t)d * 4096 + h * 64 + w0;
    for (int i = tid; i < CDIM * 32; i += 128) {
        int c = i >> 5, t = i & 31;
        sm[c][t] = xb[(size_t)c * SP + t];
    }
    __syncthreads();

    if (tid < 32) {
        float s = 0.f, ss = 0.f;
        #pragma unroll
        for (int c = 0; c < CDIM; c++) { float v = sm[c][tid]; s += v; ss += v * v; }
        float mean = s * (1.f / CDIM);
        float var  = ss * (1.f / CDIM) - mean * mean;
        s_mean[tid] = mean;
        s_rstd[tid] = rsqrtf(var + 1e-5f);
        int w  = w0 + tid;
        int ds = (d + DD - 2) & (DD - 1);
        int hs = (h + HH - 2) & (HH - 1);
        int ws = (w + WWD - 2) & (WWD - 1);
        int widx  = ((ds >> 2) * 16 + (hs >> 2)) * 16 + (ws >> 2);
        int inner = ((ds & 3) * 16) + ((hs & 3) * 4) + (ws & 3);
        s_row[tid] = (b * NWIN + widx) * NWT + inner;
    }
    __syncthreads();

    for (int i = tid; i < 32 * CDIM; i += 128) {
        int t = i / CDIM, c = i - t * CDIM;
        float v = (sm[c][t] - s_mean[t]) * s_rstd[t] * gw[c] + gb[c];
        g_xw[(size_t)s_row[t] * CDIM + c] = v;
    }
}

// ============================================================
// TF32 tensor-core GEMM: C[M,Nc] = A[M,K] @ W[Nc,K]^T + bias (+GELU)
// 128x96 block tile, 256 threads = 8 warps (4 M x 2 N), warp = 32x48,
// per-warp 2x6 m16n8k8 tf32 mma tiles. K-chunk 32. Smem pad=4 -> LDS
// fragment loads are bank-conflict-free (bank = (4g + t4) % 32).
// ============================================================
#define KC 32
#define APITCH (KC + 4)    // 36

__device__ __forceinline__ uint32_t f2tf(float x) {
    uint32_t r;
    asm("cvt.rna.tf32.f32 %0, %1;" : "=r"(r) : "f"(x));
    return r;
}

__device__ __forceinline__ void mma_tf32(float c[4], const uint32_t a[4], const uint32_t b[2]) {
    asm volatile(
        "mma.sync.aligned.m16n8k8.row.col.f32.tf32.tf32.f32 "
        "{%0,%1,%2,%3}, {%4,%5,%6,%7}, {%8,%9}, {%0,%1,%2,%3};\n"
        : "+f"(c[0]), "+f"(c[1]), "+f"(c[2]), "+f"(c[3])
        : "r"(a[0]), "r"(a[1]), "r"(a[2]), "r"(a[3]), "r"(b[0]), "r"(b[1]));
}

__global__ void __launch_bounds__(256)
k_gemm_tf32(const float* __restrict__ A, const float* __restrict__ Wt,
            const float* __restrict__ bias, float* __restrict__ Cout,
            int K, int Nc, int act)
{
    __shared__ uint32_t As[128 * APITCH];
    __shared__ uint32_t Bs[96 * APITCH];

    int tid  = threadIdx.x;
    int warp = tid >> 5, lane = tid & 31;
    int g    = lane >> 2, t4 = lane & 3;
    int wm   = warp >> 1;          // 0..3  -> M offset wm*32
    int wn   = warp & 1;           // 0..1  -> N offset wn*48
    size_t bm = (size_t)blockIdx.y * 128;
    int    bn = blockIdx.x * 96;

    float acc[2][6][4];
    #pragma unroll
    for (int i = 0; i < 2; i++)
        #pragma unroll
        for (int j = 0; j < 6; j++)
            #pragma unroll
            for (int r = 0; r < 4; r++) acc[i][j][r] = 0.f;

    for (int k0 = 0; k0 < K; k0 += KC) {
        // stage A tile 128 x 32 (1024 float4, 4 per thread)
        #pragma unroll
        for (int r = 0; r < 4; r++) {
            int i   = tid + r * 256;
            int row = i >> 3;
            int kc  = (i & 7) << 2;
            float4 v = *(const float4*)&A[(bm + row) * K + k0 + kc];
            uint4 u = make_uint4(f2tf(v.x), f2tf(v.y), f2tf(v.z), f2tf(v.w));
            *(uint4*)&As[row * APITCH + kc] = u;
        }
        // stage B tile 96 x 32 (768 float4, 3 per thread)
        #pragma unroll
        for (int r = 0; r < 3; r++) {
            int i   = tid + r * 256;
            int row = i >> 3;
            int kc  = (i & 7) << 2;
            float4 v = *(const float4*)&Wt[(size_t)(bn + row) * K + k0 + kc];
            uint4 u = make_uint4(f2tf(v.x), f2tf(v.y), f2tf(v.z), f2tf(v.w));
            *(uint4*)&Bs[row * APITCH + kc] = u;
        }
        __syncthreads();

        #pragma unroll
        for (int ks = 0; ks < 4; ks++) {
            int k8 = ks * 8;
            uint32_t af[2][4];
            #pragma unroll
            for (int mt = 0; mt < 2; mt++) {
                int rb = wm * 32 + mt * 16;
                af[mt][0] = As[(rb + g    ) * APITCH + k8 + t4    ];
                af[mt][1] = As[(rb + g + 8) * APITCH + k8 + t4    ];
                af[mt][2] = As[(rb + g    ) * APITCH + k8 + t4 + 4];
                af[mt][3] = As[(rb + g + 8) * APITCH + k8 + t4 + 4];
            }
            uint32_t bf[6][2];
            #pragma unroll
            for (int nt = 0; nt < 6; nt++) {
                int nb = wn * 48 + nt * 8;
                bf[nt][0] = Bs[(nb + g) * APITCH + k8 + t4    ];
                bf[nt][1] = Bs[(nb + g) * APITCH + k8 + t4 + 4];
            }
            #pragma unroll
            for (int mt = 0; mt < 2; mt++)
                #pragma unroll
                for (int nt = 0; nt < 6; nt++)
                    mma_tf32(acc[mt][nt], af[mt], bf[nt]);
        }
        __syncthreads();
    }

    // epilogue: c0 (row g, col 2*t4), c1 (+1), c2/c3 (row g+8)
    #pragma unroll
    for (int mt = 0; mt < 2; mt++) {
        #pragma unroll
        for (int nt = 0; nt < 6; nt++) {
            int ncol = bn + wn * 48 + nt * 8 + t4 * 2;
            #pragma unroll
            for (int half = 0; half < 2; half++) {
                size_t row = bm + wm * 32 + mt * 16 + g + half * 8;
                float v0 = acc[mt][nt][half * 2 + 0] + bias[ncol];
                float v1 = acc[mt][nt][half * 2 + 1] + bias[ncol + 1];
                if (act) {
                    v0 = 0.5f * v0 * (1.f + erff(v0 * 0.70710678118654752f));
                    v1 = 0.5f * v1 * (1.f + erff(v1 * 0.70710678118654752f));
                }
                *(float2*)&Cout[row * Nc + ncol] = make_float2(v0, v1);
            }
        }
    }
}

// ============================================================
// K3: windowed attention. Block = (window bn, head hh), 64 threads,
// one softmax row per thread. Bias + shift-mask computed analytically.
// ============================================================
__global__ void __launch_bounds__(64)
k_attn(const float* __restrict__ rpb)
{
    __shared__ float kk[NWT][HDIM];
    __shared__ float vv[NWT][HDIM];
    __shared__ float bcol[343];
    __shared__ int   gtok[NWT];

    int bn  = blockIdx.x;
    int hh  = blockIdx.y;
    int tid = threadIdx.x;   // 64

    const float* qkvb = g_qkv + (size_t)bn * NWT * (3 * CDIM) + hh * HDIM;
    for (int i = tid; i < NWT * HDIM; i += 64) {
        int j = i / HDIM, dd = i - j * HDIM;
        kk[j][dd] = qkvb[j * (3 * CDIM) +  CDIM      + dd];
        vv[j][dd] = qkvb[j * (3 * CDIM) + (2 * CDIM) + dd];
    }
    for (int i = tid; i < 343; i += 64) bcol[i] = rpb[i * NHEAD + hh];

    int widx = bn & (NWIN - 1);
    int wd = widx >> 8, wh = (widx >> 4) & 15, ww = widx & 15;
    int id = tid >> 4, ih = (tid >> 2) & 3, iw = tid & 3;
    int da = wd * 4 + id, ha = wh * 4 + ih, wa = ww * 4 + iw;
    int rd = (da < DD  - 4) ? 0 : ((da < DD  - 2) ? 1 : 2);
    int rh = (ha < HH  - 4) ? 0 : ((ha < HH  - 2) ? 1 : 2);
    int rw = (wa < WWD - 4) ? 0 : ((wa < WWD - 2) ? 1 : 2);
    gtok[tid] = rd * 9 + rh * 3 + rw;

    float q[HDIM];
    #pragma unroll
    for (int dd = 0; dd < HDIM; dd++)
        q[dd] = qkvb[tid * (3 * CDIM) + dd] * 0.2041241452319315f;  // 24^-0.5
    __syncthreads();

    int mygrp = gtok[tid];
    float s[NWT];
    float mx = -1e30f;
    #pragma unroll
    for (int j = 0; j < NWT; j++) {
        float a = 0.f;
        #pragma unroll
        for (int dd = 0; dd < HDIM; dd++)
            a = fmaf(q[dd], kk[j][dd], a);
        int jd = j >> 4, jh = (j >> 2) & 3, jw = j & 3;
        int rel = (id - jd + 3) * 49 + (ih - jh + 3) * 7 + (iw - jw + 3);
        a += bcol[rel];
        if (gtok[j] != mygrp) a -= 100.f;
        s[j] = a;
        mx = fmaxf(mx, a);
    }
    float sum = 0.f;
    #pragma unroll
    for (int j = 0; j < NWT; j++) { float e = __expf(s[j] - mx); s[j] = e; sum += e; }
    float inv = 1.f / sum;

    float o[HDIM];
    #pragma unroll
    for (int dd = 0; dd < HDIM; dd++) o[dd] = 0.f;
    #pragma unroll
    for (int j = 0; j < NWT; j++) {
        float p = s[j];
        #pragma unroll
        for (int dd = 0; dd < HDIM; dd++)
            o[dd] = fmaf(p, vv[j][dd], o[dd]);
    }
    float* op = g_att + ((size_t)bn * NWT + tid) * CDIM + hh * HDIM;
    #pragma unroll
    for (int dd = 0; dd < HDIM; dd++) op[dd] = o[dd] * inv;
}

// ============================================================
// K4: window reverse + roll(+2) + residual add + LN2.
// ============================================================
__global__ void k_res_ln2(const float* __restrict__ x,
                          const float* __restrict__ g2,
                          const float* __restrict__ b2)
{
    __shared__ float sm[CDIM][33];
    __shared__ float s_mean[32], s_rstd[32];
    __shared__ int   s_row[32];

    int blk = blockIdx.x;
    int wt  = blk & 1;
    int h   = (blk >> 1) & 63;
    int d   = (blk >> 7) & 31;
    int b   = blk >> 12;
    int w0  = wt * 32;
    int tid = threadIdx.x;   // 128

    if (tid < 32) {
        int w  = w0 + tid;
        int ds = (d + DD - 2) & (DD - 1);
        int hs = (h + HH - 2) & (HH - 1);
        int ws = (w + WWD - 2) & (WWD - 1);
        int widx  = ((ds >> 2) * 16 + (hs >> 2)) * 16 + (ws >> 2);
        int inner = ((ds & 3) * 16) + ((hs & 3) * 4) + (ws & 3);
        s_row[tid] = (b * NWIN + widx) * NWT + inner;
    }
    const float* xb = x + (size_t)b * CDIM * SP + (size_t)d * 4096 + h * 64 + w0;
    for (int i = tid; i < CDIM * 32; i += 128) {
        int c = i >> 5, t = i & 31;
        sm[c][t] = xb[(size_t)c * SP + t];
    }
    __syncthreads();
    for (int i = tid; i < 32 * CDIM; i += 128) {
        int t = i / CDIM, c = i - t * CDIM;
        sm[c][t] += g_proj[(size_t)s_row[t] * CDIM + c];
    }
    __syncthreads();
    if (tid < 32) {
        float s = 0.f, ss = 0.f;
        #pragma unroll
        for (int c = 0; c < CDIM; c++) { float v = sm[c][tid]; s += v; ss += v * v; }
        float mean = s * (1.f / CDIM);
        s_mean[tid] = mean;
        s_rstd[tid] = rsqrtf(ss * (1.f / CDIM) - mean * mean + 1e-5f);
    }
    __syncthreads();
    size_t tokbase = (size_t)b * SP + (size_t)d * 4096 + h * 64 + w0;
    for (int i = tid; i < 32 * CDIM; i += 128) {
        int t = i / CDIM, c = i - t * CDIM;
        float v = sm[c][t];
        size_t off = (tokbase + t) * CDIM + c;
        g_x2[off] = v;
        g_hn[off] = (v - s_mean[t]) * s_rstd[t] * g2[c] + b2[c];
    }
}

// ============================================================
// K7: final residual + transpose to (B, C, D, H, W)
// ============================================================
__global__ void k_final(float* __restrict__ out)
{
    __shared__ float sm[CDIM][33];
    int blk = blockIdx.x;
    int wt  = blk & 1;
    int h   = (blk >> 1) & 63;
    int d   = (blk >> 7) & 31;
    int b   = blk >> 12;
    int w0  = wt * 32;
    int tid = threadIdx.x;   // 128

    size_t tokbase = (size_t)b * SP + (size_t)d * 4096 + h * 64 + w0;
    for (int i = tid; i < 32 * CDIM; i += 128) {
        int t = i / CDIM, c = i - t * CDIM;
        size_t off = (tokbase + t) * CDIM + c;
        sm[c][t] = g_x2[off] + g_m2[off];
    }
    __syncthreads();
    float* ob = out + (size_t)b * CDIM * SP + (size_t)d * 4096 + h * 64 + w0;
    for (int i = tid; i < CDIM * 32; i += 128) {
        int c = i >> 5, t = i & 31;
        ob[(size_t)c * SP + t] = sm[c][t];
    }
}

// ============================================================
// launch
// ============================================================
extern "C" void kernel_launch(void* const* d_in, const int* in_sizes, int n_in,
                              void* d_out, int out_size)
{
    const float* x    = (const float*)d_in[0];
    const float* n1g  = (const float*)d_in[1];
    const float* n1b  = (const float*)d_in[2];
    const float* qkvw = (const float*)d_in[3];
    const float* qkvb = (const float*)d_in[4];
    const float* rpb  = (const float*)d_in[5];
    const float* pw   = (const float*)d_in[6];
    const float* pb   = (const float*)d_in[7];
    const float* n2g  = (const float*)d_in[8];
    const float* n2b  = (const float*)d_in[9];
    const float* f1w  = (const float*)d_in[10];
    const float* f1b  = (const float*)d_in[11];
    const float* f2w  = (const float*)d_in[12];
    const float* f2b  = (const float*)d_in[13];
    float* out = (float*)d_out;

    float *p_xw, *p_qkv, *p_att, *p_proj, *p_hn, *p_m1, *p_m2;
    cudaGetSymbolAddress((void**)&p_xw,  g_xw);
    cudaGetSymbolAddress((void**)&p_qkv, g_qkv);
    cudaGetSymbolAddress((void**)&p_att, g_att);
    cudaGetSymbolAddress((void**)&p_proj,g_proj);
    cudaGetSymbolAddress((void**)&p_hn,  g_hn);
    cudaGetSymbolAddress((void**)&p_m1,  g_m1);
    cudaGetSymbolAddress((void**)&p_m2,  g_m2);

    const int nblk_sp = BATCH * DD * HH * (WWD / 32);   // 8192

    // 1. LN1 + roll + window partition
    k_ln1_window<<<nblk_sp, 128>>>(x, n1g, n1b);

    // 2. qkv GEMM: (262144 x 96) @ (288 x 96)^T
    k_gemm_tf32<<<dim3(3, NTOK / 128), 256>>>(p_xw, qkvw, qkvb, p_qkv, 96, 288, 0);

    // 3. attention
    k_attn<<<dim3(BATCH * NWIN, NHEAD), 64>>>(rpb);

    // 4. proj GEMM: (262144 x 96) @ (96 x 96)^T
    k_gemm_tf32<<<dim3(1, NTOK / 128), 256>>>(p_att, pw, pb, p_proj, 96, 96, 0);

    // 5. reverse window + roll back + residual + LN2
    k_res_ln2<<<nblk_sp, 128>>>(x, n2g, n2b);

    // 6. fc1 GEMM + GELU: (262144 x 96) @ (384 x 96)^T
    k_gemm_tf32<<<dim3(4, NTOK / 128), 256>>>(p_hn, f1w, f1b, p_m1, 96, 384, 1);

    // 7. fc2 GEMM: (262144 x 384) @ (96 x 384)^T
    k_gemm_tf32<<<dim3(1, NTOK / 128), 256>>>(p_m1, f2w, f2b, p_m2, 384, 96, 0);

    // 8. final residual + transpose to (B, C, D, H, W)
    k_final<<<nblk_sp, 128>>>(out);
}

// round 3
// speedup vs baseline: 2.6167x; 1.4530x over previous
#include <cuda_runtime.h>
#include <cuda_bf16.h>
#include <math.h>
#include <stdint.h>

// ---------------- problem constants ----------------
#define CDIM   96
#define DD     32
#define HH     64
#define WWD    64
#define BATCH  2
#define SP     131072              // D*H*W
#define NTOK   (BATCH * SP)        // 262144 tokens
#define NWIN   2048                // windows per batch
#define NHEAD  4
#define HDIM   24
#define NWT    64                  // tokens per window

// ---------------- device scratch ----------------
__device__ __nv_bfloat16 g_xw  [(size_t)NTOK * CDIM];      // LN1+roll+window   (win-token-major)
__device__ __nv_bfloat16 g_qkv [(size_t)NTOK * 3 * CDIM];  // qkv               (win-token-major)
__device__ __nv_bfloat16 g_att [(size_t)NTOK * CDIM];      // attention out     (win-token-major)
__device__ __nv_bfloat16 g_proj[(size_t)NTOK * CDIM];      // proj out          (win-token-major)
__device__ float         g_x2  [(size_t)NTOK * CDIM];      // residual, CHANNEL-major (B,C,SP)
__device__ __nv_bfloat16 g_hn  [(size_t)NTOK * CDIM];      // LN2 out           (spatial token-major)
__device__ __nv_bfloat16 g_m1  [(size_t)NTOK * 4 * CDIM];  // fc1+gelu out

__device__ __forceinline__ uint32_t packbf(float a, float b) {
    __nv_bfloat162 h = __floats2bfloat162_rn(a, b);
    return *reinterpret_cast<uint32_t*>(&h);
}
__device__ __forceinline__ float2 unpackbf(uint32_t u) {
    return __bfloat1622float2(*reinterpret_cast<const __nv_bfloat162*>(&u));
}

// ============================================================
// K1: LN1 + roll(-2) + window partition -> bf16
// ============================================================
__global__ void k_ln1_window(const float* __restrict__ x,
                             const float* __restrict__ gw,
                             const float* __restrict__ gb)
{
    __shared__ float sm[CDIM][33];
    __shared__ float s_mean[32], s_rstd[32];
    __shared__ int   s_row[32];

    int blk = blockIdx.x;
    int wt  = blk & 1;
    int h   = (blk >> 1) & 63;
    int d   = (blk >> 7) & 31;
    int b   = blk >> 12;
    int w0  = wt * 32;
    int tid = threadIdx.x;   // 128

    const float* xb = x + (size_t)b * CDIM * SP + (size_t)d * 4096 + h * 64 + w0;
    for (int i = tid; i < CDIM * 32; i += 128) {
        int c = i >> 5, t = i & 31;
        sm[c][t] = xb[(size_t)c * SP + t];
    }
    __syncthreads();

    if (tid < 32) {
        float s = 0.f, ss = 0.f;
        #pragma unroll
        for (int c = 0; c < CDIM; c++) { float v = sm[c][tid]; s += v; ss += v * v; }
        float mean = s * (1.f / CDIM);
        float var  = ss * (1.f / CDIM) - mean * mean;
        s_mean[tid] = mean;
        s_rstd[tid] = rsqrtf(var + 1e-5f);
        int w  = w0 + tid;
        int ds = (d + DD - 2) & (DD - 1);
        int hs = (h + HH - 2) & (HH - 1);
        int ws = (w + WWD - 2) & (WWD - 1);
        int widx  = ((ds >> 2) * 16 + (hs >> 2)) * 16 + (ws >> 2);
        int inner = ((ds & 3) * 16) + ((hs & 3) * 4) + (ws & 3);
        s_row[tid] = (b * NWIN + widx) * NWT + inner;
    }
    __syncthreads();

    for (int i = tid; i < 32 * CDIM; i += 128) {
        int t = i / CDIM, c = i - t * CDIM;
        float v = (sm[c][t] - s_mean[t]) * s_rstd[t] * gw[c] + gb[c];
        g_xw[(size_t)s_row[t] * CDIM + c] = __float2bfloat16_rn(v);
    }
}

// ============================================================
// bf16 tensor-core GEMM: C = A[M,K](bf16) @ W[Nc,K](f32)^T + bias (+GELU)
// 128x96 block tile, 8 warps (4M x 2N), warp 32x48 = 2x6 m16n8k16 tiles.
// KC=32 (2 ksteps). Smem u32 pitch 20 -> conflict-free fragment LDS.
// ============================================================
#define KC 32
#define PITCH 20

__device__ __forceinline__ void mma_bf16(float c[4], const uint32_t a[4], const uint32_t b[2]) {
    asm volatile(
        "mma.sync.aligned.m16n8k16.row.col.f32.bf16.bf16.f32 "
        "{%0,%1,%2,%3}, {%4,%5,%6,%7}, {%8,%9}, {%0,%1,%2,%3};\n"
        : "+f"(c[0]), "+f"(c[1]), "+f"(c[2]), "+f"(c[3])
        : "r"(a[0]), "r"(a[1]), "r"(a[2]), "r"(a[3]), "r"(b[0]), "r"(b[1]));
}

// common mainloop producing acc[2][6][4] for (bm, bn)
#define GEMM_MAINLOOP(A, Wt, K)                                                 \
    for (int k0 = 0; k0 < (K); k0 += KC) {                                      \
        _Pragma("unroll")                                                       \
        for (int r = 0; r < 2; r++) {                                           \
            int i   = tid + r * 256;                                            \
            int row = i >> 2;                                                   \
            int q   = i & 3;                                                    \
            uint4 u = ((const uint4*)((A) + (bm + row) * (K) + k0))[q];         \
            *(uint4*)&As[row * PITCH + q * 4] = u;                              \
        }                                                                       \
        _Pragma("unroll")                                                       \
        for (int r = 0; r < 3; r++) {                                           \
            int i   = tid + r * 256;                                            \
            int row = i >> 3;                                                   \
            int kc4 = i & 7;                                                    \
            float4 v = *(const float4*)&(Wt)[(size_t)(bn + row) * (K) + k0 + kc4 * 4]; \
            uint2 u = make_uint2(packbf(v.x, v.y), packbf(v.z, v.w));           \
            *(uint2*)&Bs[row * PITCH + kc4 * 2] = u;                            \
        }                                                                       \
        __syncthreads();                                                        \
        _Pragma("unroll")                                                       \
        for (int ks = 0; ks < 2; ks++) {                                        \
            int k8 = ks * 8;                                                    \
            uint32_t af[2][4];                                                  \
            _Pragma("unroll")                                                   \
            for (int mt = 0; mt < 2; mt++) {                                    \
                int rb = wm * 32 + mt * 16;                                     \
                af[mt][0] = As[(rb + g    ) * PITCH + k8 + t4    ];             \
                af[mt][1] = As[(rb + g + 8) * PITCH + k8 + t4    ];             \
                af[mt][2] = As[(rb + g    ) * PITCH + k8 + t4 + 4];             \
                af[mt][3] = As[(rb + g + 8) * PITCH + k8 + t4 + 4];             \
            }                                                                   \
            uint32_t bf[6][2];                                                  \
            _Pragma("unroll")                                                   \
            for (int nt = 0; nt < 6; nt++) {                                    \
                int nb = wn * 48 + nt * 8;                                      \
                bf[nt][0] = Bs[(nb + g) * PITCH + k8 + t4    ];                 \
                bf[nt][1] = Bs[(nb + g) * PITCH + k8 + t4 + 4];                 \
            }                                                                   \
            _Pragma("unroll")                                                   \
            for (int mt = 0; mt < 2; mt++)                                      \
                _Pragma("unroll")                                               \
                for (int nt = 0; nt < 6; nt++)                                  \
                    mma_bf16(acc[mt][nt], af[mt], bf[nt]);                      \
        }                                                                       \
        __syncthreads();                                                        \
    }

__global__ void __launch_bounds__(256)
k_gemm_bf16(const __nv_bfloat16* __restrict__ A, const float* __restrict__ Wt,
            const float* __restrict__ bias, __nv_bfloat16* __restrict__ Cout,
            int K, int Nc, int act)
{
    __shared__ __align__(16) uint32_t As[128 * PITCH];
    __shared__ __align__(16) uint32_t Bs[96 * PITCH];

    int tid  = threadIdx.x;
    int warp = tid >> 5, lane = tid & 31;
    int g    = lane >> 2, t4 = lane & 3;
    int wm   = warp >> 1;
    int wn   = warp & 1;
    size_t bm = (size_t)blockIdx.y * 128;
    int    bn = blockIdx.x * 96;

    float acc[2][6][4];
    #pragma unroll
    for (int i = 0; i < 2; i++)
        #pragma unroll
        for (int j = 0; j < 6; j++)
            #pragma unroll
            for (int r = 0; r < 4; r++) acc[i][j][r] = 0.f;

    GEMM_MAINLOOP(A, Wt, K)

    #pragma unroll
    for (int mt = 0; mt < 2; mt++) {
        #pragma unroll
        for (int nt = 0; nt < 6; nt++) {
            int ncol = bn + wn * 48 + nt * 8 + t4 * 2;
            #pragma unroll
            for (int half = 0; half < 2; half++) {
                size_t row = bm + wm * 32 + mt * 16 + g + half * 8;
                float v0 = acc[mt][nt][half * 2 + 0] + bias[ncol];
                float v1 = acc[mt][nt][half * 2 + 1] + bias[ncol + 1];
                if (act) {
                    v0 = 0.5f * v0 * (1.f + erff(v0 * 0.70710678118654752f));
                    v1 = 0.5f * v1 * (1.f + erff(v1 * 0.70710678118654752f));
                }
                *(uint32_t*)&Cout[row * Nc + ncol] = packbf(v0, v1);
            }
        }
    }
}

// fc2 GEMM fused with residual add + transpose to (B,C,D,H,W) output.
__global__ void __launch_bounds__(256)
k_gemm_fc2(const __nv_bfloat16* __restrict__ A, const float* __restrict__ Wt,
           const float* __restrict__ bias, const float* __restrict__ x2,
           float* __restrict__ out)
{
    const int K = 384;
    __shared__ __align__(16) uint32_t As[128 * PITCH];
    __shared__ __align__(16) uint32_t Bs[96 * PITCH];
    __shared__ float sout[48 * 132];

    int tid  = threadIdx.x;
    int warp = tid >> 5, lane = tid & 31;
    int g    = lane >> 2, t4 = lane & 3;
    int wm   = warp >> 1;
    int wn   = warp & 1;
    size_t bm = (size_t)blockIdx.y * 128;
    const int bn = 0;

    float acc[2][6][4];
    #pragma unroll
    for (int i = 0; i < 2; i++)
        #pragma unroll
        for (int j = 0; j < 6; j++)
            #pragma unroll
            for (int r = 0; r < 4; r++) acc[i][j][r] = 0.f;

    GEMM_MAINLOOP(A, Wt, K)

    int b   = (int)(bm >> 17);          // bm / SP
    int sp0 = (int)(bm & (SP - 1));

    #pragma unroll
    for (int p = 0; p < 2; p++) {
        if (wn == p) {
            #pragma unroll
            for (int mt = 0; mt < 2; mt++)
                #pragma unroll
                for (int nt = 0; nt < 6; nt++) {
                    int cl = nt * 8 + t4 * 2;             // 0..47
                    #pragma unroll
                    for (int half = 0; half < 2; half++) {
                        int rl = wm * 32 + mt * 16 + g + half * 8;
                        sout[(cl    ) * 132 + rl] = acc[mt][nt][half * 2 + 0] + bias[p * 48 + cl];
                        sout[(cl + 1) * 132 + rl] = acc[mt][nt][half * 2 + 1] + bias[p * 48 + cl + 1];
                    }
                }
        }
        __syncthreads();
        for (int i = tid; i < 48 * 128; i += 256) {
            int c = i >> 7, t = i & 127;
            size_t off = (size_t)b * CDIM * SP + (size_t)(p * 48 + c) * SP + sp0 + t;
            out[off] = sout[c * 132 + t] + x2[off];
        }
        __syncthreads();
    }
}

// ============================================================
// K3: windowed attention. Block = window, 256 threads = 4 heads x 64 rows.
// Un-normalized single-pass softmax (logits are O(0.1); masked -> e=0).
// ============================================================
__global__ void __launch_bounds__(256)
k_attn(const float* __restrict__ rpb)
{
    __shared__ uint32_t kk2[NHEAD][NWT][12];
    __shared__ uint32_t vv2[NHEAD][NWT][12];
    __shared__ float bcol[NHEAD][343];
    __shared__ int   gtok[NWT];

    int bn  = blockIdx.x;
    int tid = threadIdx.x;
    int hh  = tid >> 6;
    int tok = tid & 63;

    const __nv_bfloat16* qkvb = g_qkv + (size_t)bn * NWT * (3 * CDIM);

    for (int i = tid; i < NHEAD * NWT * 12; i += 256) {
        int h = i / (NWT * 12);
        int r = i - h * (NWT * 12);
        int j = r / 12, p = r - j * 12;
        const uint32_t* base = (const uint32_t*)(qkvb + (size_t)j * 288);
        kk2[h][j][p] = base[48 + h * 12 + p];
        vv2[h][j][p] = base[96 + h * 12 + p];
    }
    for (int i = tid; i < NHEAD * 343; i += 256) {
        int h = i / 343, r = i - h * 343;
        bcol[h][r] = rpb[r * NHEAD + h];
    }
    if (tid < NWT) {
        int widx = bn & (NWIN - 1);
        int wd = widx >> 8, wh = (widx >> 4) & 15, ww = widx & 15;
        int id = tid >> 4, ih = (tid >> 2) & 3, iw = tid & 3;
        int da = wd * 4 + id, ha = wh * 4 + ih, wa = ww * 4 + iw;
        int rd = (da < DD  - 4) ? 0 : ((da < DD  - 2) ? 1 : 2);
        int rh = (ha < HH  - 4) ? 0 : ((ha < HH  - 2) ? 1 : 2);
        int rw = (wa < WWD - 4) ? 0 : ((wa < WWD - 2) ? 1 : 2);
        gtok[tid] = rd * 9 + rh * 3 + rw;
    }

    float q[HDIM];
    {
        const uint32_t* base = (const uint32_t*)(qkvb + (size_t)tok * 288);
        #pragma unroll
        for (int p = 0; p < 12; p++) {
            float2 f = unpackbf(base[hh * 12 + p]);
            q[2 * p    ] = f.x * 0.2041241452319315f;
            q[2 * p + 1] = f.y * 0.2041241452319315f;
        }
    }
    __syncthreads();

    int id = tok >> 4, ih = (tok >> 2) & 3, iw = tok & 3;
    int mygrp = gtok[tok];

    float o[HDIM];
    #pragma unroll
    for (int dd = 0; dd < HDIM; dd++) o[dd] = 0.f;
    float sum = 0.f;

    #pragma unroll 4
    for (int j = 0; j < NWT; j++) {
        float a = 0.f;
        #pragma unroll
        for (int p = 0; p < 12; p++) {
            float2 kf = unpackbf(kk2[hh][j][p]);
            a = fmaf(q[2 * p], kf.x, a);
            a = fmaf(q[2 * p + 1], kf.y, a);
        }
        int jd = j >> 4, jh = (j >> 2) & 3, jw = j & 3;
        int rel = (id - jd + 3) * 49 + (ih - jh + 3) * 7 + (iw - jw + 3);
        a += bcol[hh][rel];
        float e = (gtok[j] == mygrp) ? __expf(a) : 0.f;
        sum += e;
        #pragma unroll
        for (int p = 0; p < 12; p++) {
            float2 vf = unpackbf(vv2[hh][j][p]);
            o[2 * p]     = fmaf(e, vf.x, o[2 * p]);
            o[2 * p + 1] = fmaf(e, vf.y, o[2 * p + 1]);
        }
    }
    float inv = 1.f / sum;

    uint32_t* op = (uint32_t*)(g_att + ((size_t)bn * NWT + tok) * CDIM + hh * HDIM);
    #pragma unroll
    for (int p = 0; p < 12; p++)
        op[p] = packbf(o[2 * p] * inv, o[2 * p + 1] * inv);
}

// ============================================================
// K4: window reverse + roll(+2) + residual + LN2.
// Writes g_x2 fp32 CHANNEL-major, g_hn bf16 token-major.
// ============================================================
__global__ void k_res_ln2(const float* __restrict__ x,
                          const float* __restrict__ g2,
                          const float* __restrict__ b2)
{
    __shared__ float sm[CDIM][33];
    __shared__ float s_mean[32], s_rstd[32];
    __shared__ int   s_row[32];

    int blk = blockIdx.x;
    int wt  = blk & 1;
    int h   = (blk >> 1) & 63;
    int d   = (blk >> 7) & 31;
    int b   = blk >> 12;
    int w0  = wt * 32;
    int tid = threadIdx.x;   // 128

    if (tid < 32) {
        int w  = w0 + tid;
        int ds = (d + DD - 2) & (DD - 1);
        int hs = (h + HH - 2) & (HH - 1);
        int ws = (w + WWD - 2) & (WWD - 1);
        int widx  = ((ds >> 2) * 16 + (hs >> 2)) * 16 + (ws >> 2);
        int inner = ((ds & 3) * 16) + ((hs & 3) * 4) + (ws & 3);
        s_row[tid] = (b * NWIN + widx) * NWT + inner;
    }
    const float* xb = x + (size_t)b * CDIM * SP + (size_t)d * 4096 + h * 64 + w0;
    for (int i = tid; i < CDIM * 32; i += 128) {
        int c = i >> 5, t = i & 31;
        sm[c][t] = xb[(size_t)c * SP + t];
    }
    __syncthreads();
    for (int i = tid; i < 32 * CDIM; i += 128) {
        int t = i / CDIM, c = i - t * CDIM;
        sm[c][t] += __bfloat162float(g_proj[(size_t)s_row[t] * CDIM + c]);
    }
    __syncthreads();
    if (tid < 32) {
        float s = 0.f, ss = 0.f;
        #pragma unroll
        for (int c = 0; c < CDIM; c++) { float v = sm[c][tid]; s += v; ss += v * v; }
        float mean = s * (1.f / CDIM);
        s_mean[tid] = mean;
        s_rstd[tid] = rsqrtf(ss * (1.f / CDIM) - mean * mean + 1e-5f);
    }
    __syncthreads();
    // x2 channel-major (coalesced)
    float* x2b = g_x2 + (size_t)b * CDIM * SP + (size_t)d * 4096 + h * 64 + w0;
    for (int i = tid; i < CDIM * 32; i += 128) {
        int c = i >> 5, t = i & 31;
        x2b[(size_t)c * SP + t] = sm[c][t];
    }
    // hn token-major bf16
    size_t tokbase = (size_t)b * SP + (size_t)d * 4096 + h * 64 + w0;
    for (int i = tid; i < 32 * CDIM; i += 128) {
        int t = i / CDIM, c = i - t * CDIM;
        float v = (sm[c][t] - s_mean[t]) * s_rstd[t] * g2[c] + b2[c];
        g_hn[(tokbase + t) * CDIM + c] = __float2bfloat16_rn(v);
    }
}

// ============================================================
// launch
// ============================================================
extern "C" void kernel_launch(void* const* d_in, const int* in_sizes, int n_in,
                              void* d_out, int out_size)
{
    const float* x    = (const float*)d_in[0];
    const float* n1g  = (const float*)d_in[1];
    const float* n1b  = (const float*)d_in[2];
    const float* qkvw = (const float*)d_in[3];
    const float* qkvb = (const float*)d_in[4];
    const float* rpb  = (const float*)d_in[5];
    const float* pw   = (const float*)d_in[6];
    const float* pb   = (const float*)d_in[7];
    const float* n2g  = (const float*)d_in[8];
    const float* n2b  = (const float*)d_in[9];
    const float* f1w  = (const float*)d_in[10];
    const float* f1b  = (const float*)d_in[11];
    const float* f2w  = (const float*)d_in[12];
    const float* f2b  = (const float*)d_in[13];
    float* out = (float*)d_out;

    __nv_bfloat16 *p_xw, *p_qkv, *p_att, *p_hn, *p_m1;
    float *p_x2;
    cudaGetSymbolAddress((void**)&p_xw,  g_xw);
    cudaGetSymbolAddress((void**)&p_qkv, g_qkv);
    cudaGetSymbolAddress((void**)&p_att, g_att);
    cudaGetSymbolAddress((void**)&p_hn,  g_hn);
    cudaGetSymbolAddress((void**)&p_m1,  g_m1);
    cudaGetSymbolAddress((void**)&p_x2,  g_x2);
    __nv_bfloat16 *p_proj;
    cudaGetSymbolAddress((void**)&p_proj, g_proj);

    const int nblk_sp = BATCH * DD * HH * (WWD / 32);   // 8192

    k_ln1_window<<<nblk_sp, 128>>>(x, n1g, n1b);
    k_gemm_bf16<<<dim3(3, NTOK / 128), 256>>>(p_xw, qkvw, qkvb, p_qkv, 96, 288, 0);
    k_attn<<<BATCH * NWIN, 256>>>(rpb);
    k_gemm_bf16<<<dim3(1, NTOK / 128), 256>>>(p_att, pw, pb, p_proj, 96, 96, 0);
    k_res_ln2<<<nblk_sp, 128>>>(x, n2g, n2b);
    k_gemm_bf16<<<dim3(4, NTOK / 128), 256>>>(p_hn, f1w, f1b, p_m1, 96, 384, 1);
    k_gemm_fc2<<<dim3(1, NTOK / 128), 256>>>(p_m1, f2w, f2b, p_x2, out);
}

// round 4
// speedup vs baseline: 2.8180x; 1.0769x over previous
#include <cuda_runtime.h>
#include <cuda_bf16.h>
#include <math.h>
#include <stdint.h>

// ---------------- problem constants ----------------
#define CDIM   96
#define DD     32
#define HH     64
#define WWD    64
#define BATCH  2
#define SP     131072
#define NTOK   (BATCH * SP)
#define NWIN   2048
#define NHEAD  4
#define HDIM   24
#define NWT    64

// ---------------- device scratch ----------------
__device__ __nv_bfloat16 g_qkv [(size_t)NTOK * 3 * CDIM];  // window-token-major
__device__ __nv_bfloat16 g_att [(size_t)NTOK * CDIM];      // window-token-major
__device__ float         g_x2  [(size_t)NTOK * CDIM];      // residual, SPATIAL token-major
__device__ __nv_bfloat16 g_hn  [(size_t)NTOK * CDIM];      // LN2 out, SPATIAL token-major
__device__ __nv_bfloat16 g_m1  [(size_t)NTOK * 4 * CDIM];  // fc1+gelu, SPATIAL token-major
// bf16 weights
__device__ __nv_bfloat16 g_wqkv[288 * 96];
__device__ __nv_bfloat16 g_wproj[96 * 96];
__device__ __nv_bfloat16 g_wfc1[384 * 96];
__device__ __nv_bfloat16 g_wfc2[96 * 384];

__device__ __forceinline__ uint32_t packbf(float a, float b) {
    __nv_bfloat162 h = __floats2bfloat162_rn(a, b);
    return *reinterpret_cast<uint32_t*>(&h);
}
__device__ __forceinline__ float2 unpackbf(uint32_t u) {
    return __bfloat1622float2(*reinterpret_cast<const __nv_bfloat162*>(&u));
}

// ---------------- weight conversion ----------------
__global__ void k_wconv(const float* __restrict__ a, const float* __restrict__ b,
                        const float* __restrict__ c, const float* __restrict__ d)
{
    int i = blockIdx.x * 256 + threadIdx.x;
    if (i < 27648)            g_wqkv[i]          = __float2bfloat16_rn(a[i]);
    else if (i < 36864)       g_wproj[i - 27648] = __float2bfloat16_rn(b[i - 27648]);
    else if (i < 73728)       g_wfc1[i - 36864]  = __float2bfloat16_rn(c[i - 36864]);
    else if (i < 110592)      g_wfc2[i - 73728]  = __float2bfloat16_rn(d[i - 73728]);
}

// ---------------- mma helpers (K=96 single-shot, pitch 52 u32) ----------------
#define PITCH 52

__device__ __forceinline__ void mma_bf16(float c[4], const uint32_t a[4], const uint32_t b[2]) {
    asm volatile(
        "mma.sync.aligned.m16n8k16.row.col.f32.bf16.bf16.f32 "
        "{%0,%1,%2,%3}, {%4,%5,%6,%7}, {%8,%9}, {%0,%1,%2,%3};\n"
        : "+f"(c[0]), "+f"(c[1]), "+f"(c[2]), "+f"(c[3])
        : "r"(a[0]), "r"(a[1]), "r"(a[2]), "r"(a[3]), "r"(b[0]), "r"(b[1]));
}

__device__ __forceinline__ void mma_tile96(const uint32_t* As, const uint32_t* Bs,
                                           float acc[2][6][4], int g, int t4, int wm, int wn)
{
    #pragma unroll
    for (int ks = 0; ks < 6; ks++) {
        int k8 = ks * 8;
        uint32_t af[2][4];
        #pragma unroll
        for (int mt = 0; mt < 2; mt++) {
            int rb = wm * 32 + mt * 16;
            af[mt][0] = As[(rb + g    ) * PITCH + k8 + t4    ];
            af[mt][1] = As[(rb + g + 8) * PITCH + k8 + t4    ];
            af[mt][2] = As[(rb + g    ) * PITCH + k8 + t4 + 4];
            af[mt][3] = As[(rb + g + 8) * PITCH + k8 + t4 + 4];
        }
        uint32_t bf[6][2];
        #pragma unroll
        for (int nt = 0; nt < 6; nt++) {
            int nb = wn * 48 + nt * 8;
            bf[nt][0] = Bs[(nb + g) * PITCH + k8 + t4    ];
            bf[nt][1] = Bs[(nb + g) * PITCH + k8 + t4 + 4];
        }
        #pragma unroll
        for (int mt = 0; mt < 2; mt++)
            #pragma unroll
            for (int nt = 0; nt < 6; nt++)
                mma_bf16(acc[mt][nt], af[mt], bf[nt]);
    }
}

__device__ __forceinline__ void stage_A96(const __nv_bfloat16* A, size_t bm, uint32_t* As, int tid) {
    for (int i = tid; i < 128 * 12; i += 256) {
        int row = i / 12, q = i - row * 12;
        ((uint4*)&As[row * PITCH])[q] = ((const uint4*)(A + (bm + row) * 96))[q];
    }
}
__device__ __forceinline__ void stage_B96(const __nv_bfloat16* Wb, int bn, uint32_t* Bs, int tid) {
    for (int i = tid; i < 96 * 12; i += 256) {
        int row = i / 12, q = i - row * 12;
        ((uint4*)&Bs[row * PITCH])[q] = ((const uint4*)(Wb + (size_t)(bn + row) * 96))[q];
    }
}

// decode window-token-major row r -> spatial coords (after un-shift)
__device__ __forceinline__ void decode_tok(int r, int& b, int& d, int& h, int& w) {
    int widx = r >> 6, inner = r & 63;
    b = widx >> 11;
    int wi = widx & 2047;
    int wd = wi >> 8, wh = (wi >> 4) & 15, ww = wi & 15;
    int id = inner >> 4, ih = (inner >> 2) & 3, iw = inner & 3;
    d = (wd * 4 + id + 2) & 31;
    h = (wh * 4 + ih + 2) & 63;
    w = (ww * 4 + iw + 2) & 63;
}

// ============================================================
// K1: fused LN1 + roll + window + qkv GEMM (3 N-tiles in-block)
// ============================================================
__global__ void __launch_bounds__(256)
k_qkv(const float* __restrict__ x, const float* __restrict__ gw,
      const float* __restrict__ gb, const float* __restrict__ qbias)
{
    extern __shared__ char smem[];
    uint32_t* As = (uint32_t*)smem;                // 128*52 u32 = 26624B
    uint32_t* Bs = (uint32_t*)(smem + 26624);      // 96*52  u32 = 19968B
    float* sgw = (float*)(smem + 46592);
    float* sgb = sgw + 96;

    int tid = threadIdx.x;
    if (tid < 96) { sgw[tid] = gw[tid]; sgb[tid] = gb[tid]; }

    size_t bm = (size_t)blockIdx.x * 128;
    int t = tid & 127;
    int b, d, h, w;
    decode_tok((int)bm + t, b, d, h, w);
    size_t xbase = ((size_t)b * 96) * SP + (size_t)d * 4096 + h * 64 + w;
    int c0 = tid >> 7;   // 0 or 1

    // gather x -> bf16 pairs in As
    for (int p = c0; p < 48; p += 2) {
        float v0 = x[xbase + (size_t)(2 * p) * SP];
        float v1 = x[xbase + (size_t)(2 * p + 1) * SP];
        As[t * PITCH + p] = packbf(v0, v1);
    }
    __syncthreads();

    // in-place LN over As rows
    if (tid < 128) {
        uint32_t* row = As + tid * PITCH;
        float s = 0.f, ss = 0.f;
        #pragma unroll
        for (int p = 0; p < 48; p++) {
            float2 f = unpackbf(row[p]);
            s += f.x + f.y; ss += f.x * f.x + f.y * f.y;
        }
        float mean = s * (1.f / 96.f);
        float rstd = rsqrtf(ss * (1.f / 96.f) - mean * mean + 1e-5f);
        #pragma unroll
        for (int p = 0; p < 48; p++) {
            float2 f = unpackbf(row[p]);
            f.x = (f.x - mean) * rstd * sgw[2 * p] + sgb[2 * p];
            f.y = (f.y - mean) * rstd * sgw[2 * p + 1] + sgb[2 * p + 1];
            row[p] = packbf(f.x, f.y);
        }
    }
    __syncthreads();

    int warp = tid >> 5, lane = tid & 31, g = lane >> 2, t4 = lane & 3;
    int wm = warp >> 1, wn = warp & 1;

    for (int bt = 0; bt < 3; bt++) {
        stage_B96(g_wqkv, bt * 96, Bs, tid);
        __syncthreads();
        float acc[2][6][4];
        #pragma unroll
        for (int i = 0; i < 2; i++)
            #pragma unroll
            for (int j = 0; j < 6; j++)
                #pragma unroll
                for (int r = 0; r < 4; r++) acc[i][j][r] = 0.f;
        mma_tile96(As, Bs, acc, g, t4, wm, wn);
        #pragma unroll
        for (int mt = 0; mt < 2; mt++)
            #pragma unroll
            for (int nt = 0; nt < 6; nt++) {
                int ncol = wn * 48 + nt * 8 + t4 * 2;
                #pragma unroll
                for (int half = 0; half < 2; half++) {
                    size_t row = bm + wm * 32 + mt * 16 + g + half * 8;
                    float v0 = acc[mt][nt][half * 2 + 0] + qbias[bt * 96 + ncol];
                    float v1 = acc[mt][nt][half * 2 + 1] + qbias[bt * 96 + ncol + 1];
                    *(uint32_t*)&g_qkv[row * 288 + bt * 96 + ncol] = packbf(v0, v1);
                }
            }
        __syncthreads();
    }
}

// ============================================================
// K2: windowed attention, f32 K/V in smem (float4 inner loop)
// ============================================================
__global__ void __launch_bounds__(256)
k_attn(const float* __restrict__ rpb)
{
    extern __shared__ char smem[];
    float* kk   = (float*)smem;            // [4][64][24]
    float* vv   = kk + 4 * 64 * 24;
    float* bcol = vv + 4 * 64 * 24;        // [4][344]
    int*   gtok = (int*)(bcol + 4 * 344);  // [64]

    int bn  = blockIdx.x;
    int tid = threadIdx.x;
    int hh  = tid >> 6;
    int tok = tid & 63;

    const uint32_t* qkvb = (const uint32_t*)(g_qkv + (size_t)bn * NWT * 288);

    for (int i = tid; i < 4 * 64 * 12; i += 256) {
        int hph = i / 768;
        int rem = i - hph * 768;
        int j = rem / 12, p = rem - j * 12;
        const uint32_t* base = qkvb + j * 144;
        float2 kf = unpackbf(base[48 + hph * 12 + p]);
        float2 vf = unpackbf(base[96 + hph * 12 + p]);
        kk[(hph * 64 + j) * 24 + 2 * p    ] = kf.x;
        kk[(hph * 64 + j) * 24 + 2 * p + 1] = kf.y;
        vv[(hph * 64 + j) * 24 + 2 * p    ] = vf.x;
        vv[(hph * 64 + j) * 24 + 2 * p + 1] = vf.y;
    }
    for (int i = tid; i < 4 * 343; i += 256) {
        int hph = i / 343, r = i - hph * 343;
        bcol[hph * 344 + r] = rpb[r * NHEAD + hph];
    }
    if (tid < NWT) {
        int widx = bn & (NWIN - 1);
        int wd = widx >> 8, wh = (widx >> 4) & 15, ww = widx & 15;
        int id = tid >> 4, ih = (tid >> 2) & 3, iw = tid & 3;
        int da = wd * 4 + id, ha = wh * 4 + ih, wa = ww * 4 + iw;
        int rd = (da < DD  - 4) ? 0 : ((da < DD  - 2) ? 1 : 2);
        int rh = (ha < HH  - 4) ? 0 : ((ha < HH  - 2) ? 1 : 2);
        int rw = (wa < WWD - 4) ? 0 : ((wa < WWD - 2) ? 1 : 2);
        gtok[tid] = rd * 9 + rh * 3 + rw;
    }

    float q[HDIM];
    {
        const uint32_t* base = qkvb + tok * 144;
        #pragma unroll
        for (int p = 0; p < 12; p++) {
            float2 f = unpackbf(base[hh * 12 + p]);
            q[2 * p    ] = f.x * 0.2041241452319315f;
            q[2 * p + 1] = f.y * 0.2041241452319315f;
        }
    }
    __syncthreads();

    int id = tok >> 4, ih = (tok >> 2) & 3, iw = tok & 3;
    int mygrp = gtok[tok];
    const float* bch = bcol + hh * 344;
    const float4* kf4 = (const float4*)(kk + hh * 64 * 24);
    const float4* vf4 = (const float4*)(vv + hh * 64 * 24);

    float o[HDIM];
    #pragma unroll
    for (int dd = 0; dd < HDIM; dd++) o[dd] = 0.f;
    float sum = 0.f;

    #pragma unroll 4
    for (int j = 0; j < NWT; j++) {
        const float4* kr = kf4 + j * 6;
        float a = 0.f;
        #pragma unroll
        for (int p = 0; p < 6; p++) {
            float4 kv = kr[p];
            a = fmaf(q[4 * p    ], kv.x, a);
            a = fmaf(q[4 * p + 1], kv.y, a);
            a = fmaf(q[4 * p + 2], kv.z, a);
            a = fmaf(q[4 * p + 3], kv.w, a);
        }
        int jd = j >> 4, jh = (j >> 2) & 3, jw = j & 3;
        a += bch[(id - jd + 3) * 49 + (ih - jh + 3) * 7 + (iw - jw + 3)];
        float e = (gtok[j] == mygrp) ? __expf(a) : 0.f;
        sum += e;
        const float4* vr = vf4 + j * 6;
        #pragma unroll
        for (int p = 0; p < 6; p++) {
            float4 vvec = vr[p];
            o[4 * p    ] = fmaf(e, vvec.x, o[4 * p    ]);
            o[4 * p + 1] = fmaf(e, vvec.y, o[4 * p + 1]);
            o[4 * p + 2] = fmaf(e, vvec.z, o[4 * p + 2]);
            o[4 * p + 3] = fmaf(e, vvec.w, o[4 * p + 3]);
        }
    }
    float inv = 1.f / sum;

    uint32_t* op = (uint32_t*)(g_att + ((size_t)bn * NWT + tok) * CDIM + hh * HDIM);
    #pragma unroll
    for (int p = 0; p < 12; p++)
        op[p] = packbf(o[2 * p] * inv, o[2 * p + 1] * inv);
}

// ============================================================
// K3: proj GEMM + window reverse + roll + residual + LN2
// writes g_x2 (f32) and g_hn (bf16), SPATIAL token-major
// ============================================================
__global__ void __launch_bounds__(256)
k_proj(const float* __restrict__ x, const float* __restrict__ pbias,
       const float* __restrict__ g2, const float* __restrict__ b2)
{
    extern __shared__ char smem[];
    uint32_t* As = (uint32_t*)smem;
    uint32_t* Bs = (uint32_t*)(smem + 26624);
    float* xs    = (float*)smem;                  // [128][97], reuses As/Bs
    int*   sprow = (int*)(smem + 49664);          // [128]
    float* smu   = (float*)(smem + 50176);        // [128]
    float* srs   = (float*)(smem + 50688);        // [128]
    float* sg2   = (float*)(smem + 51200);        // [96]
    float* sb2   = (float*)(smem + 51584);        // [96]

    int tid = threadIdx.x;
    if (tid < 96) { sg2[tid] = g2[tid]; sb2[tid] = b2[tid]; }

    size_t bm = (size_t)blockIdx.x * 128;
    stage_A96(g_att, bm, As, tid);
    stage_B96(g_wproj, 0, Bs, tid);
    __syncthreads();

    int warp = tid >> 5, lane = tid & 31, g = lane >> 2, t4 = lane & 3;
    int wm = warp >> 1, wn = warp & 1;

    float acc[2][6][4];
    #pragma unroll
    for (int i = 0; i < 2; i++)
        #pragma unroll
        for (int j = 0; j < 6; j++)
            #pragma unroll
            for (int r = 0; r < 4; r++) acc[i][j][r] = 0.f;
    mma_tile96(As, Bs, acc, g, t4, wm, wn);
    __syncthreads();

    // acc + bias -> xs
    #pragma unroll
    for (int mt = 0; mt < 2; mt++)
        #pragma unroll
        for (int nt = 0; nt < 6; nt++) {
            int cl = wn * 48 + nt * 8 + t4 * 2;
            #pragma unroll
            for (int half = 0; half < 2; half++) {
                int rl = wm * 32 + mt * 16 + g + half * 8;
                xs[rl * 97 + cl    ] = acc[mt][nt][half * 2 + 0] + pbias[cl];
                xs[rl * 97 + cl + 1] = acc[mt][nt][half * 2 + 1] + pbias[cl + 1];
            }
        }
    __syncthreads();

    // residual gather from x
    int t = tid & 127;
    int b, d, h, w;
    decode_tok((int)bm + t, b, d, h, w);
    int spoff = d * 4096 + h * 64 + w;
    size_t xbase = ((size_t)b * 96) * SP + spoff;
    if (tid < 128) sprow[tid] = b * SP + spoff;
    int c0 = tid >> 7;
    for (int c = c0; c < 96; c += 2)
        xs[t * 97 + c] += x[xbase + (size_t)c * SP];
    __syncthreads();

    // LN2 stats per token
    if (tid < 128) {
        const float* row = xs + tid * 97;
        float s = 0.f, ss = 0.f;
        #pragma unroll
        for (int c = 0; c < 96; c++) { float v = row[c]; s += v; ss += v * v; }
        float mean = s * (1.f / 96.f);
        smu[tid] = mean;
        srs[tid] = rsqrtf(ss * (1.f / 96.f) - mean * mean + 1e-5f);
    }
    __syncthreads();

    // write x2 (f32) and hn (bf16) per token, warp-cooperative
    #pragma unroll
    for (int tk = 0; tk < 16; tk++) {
        int tt = warp * 16 + tk;
        size_t row = (size_t)sprow[tt] * 96;
        float mu = smu[tt], rs = srs[tt];
        #pragma unroll
        for (int rep = 0; rep < 3; rep++) {
            int c = lane + rep * 32;
            float v = xs[tt * 97 + c];
            g_x2[row + c] = v;
            g_hn[row + c] = __float2bfloat16_rn((v - mu) * rs * sg2[c] + sb2[c]);
        }
    }
}

// ============================================================
// K4: fc1 GEMM + GELU (4 N-tiles in-block)
// ============================================================
__global__ void __launch_bounds__(256)
k_fc1(const float* __restrict__ f1bias)
{
    extern __shared__ char smem[];
    uint32_t* As = (uint32_t*)smem;
    uint32_t* Bs = (uint32_t*)(smem + 26624);

    int tid = threadIdx.x;
    size_t bm = (size_t)blockIdx.x * 128;
    stage_A96(g_hn, bm, As, tid);

    int warp = tid >> 5, lane = tid & 31, g = lane >> 2, t4 = lane & 3;
    int wm = warp >> 1, wn = warp & 1;

    for (int bt = 0; bt < 4; bt++) {
        if (bt) __syncthreads();
        stage_B96(g_wfc1, bt * 96, Bs, tid);
        __syncthreads();
        float acc[2][6][4];
        #pragma unroll
        for (int i = 0; i < 2; i++)
            #pragma unroll
            for (int j = 0; j < 6; j++)
                #pragma unroll
                for (int r = 0; r < 4; r++) acc[i][j][r] = 0.f;
        mma_tile96(As, Bs, acc, g, t4, wm, wn);
        #pragma unroll
        for (int mt = 0; mt < 2; mt++)
            #pragma unroll
            for (int nt = 0; nt < 6; nt++) {
                int ncol = wn * 48 + nt * 8 + t4 * 2;
                #pragma unroll
                for (int half = 0; half < 2; half++) {
                    size_t row = bm + wm * 32 + mt * 16 + g + half * 8;
                    float v0 = acc[mt][nt][half * 2 + 0] + f1bias[bt * 96 + ncol];
                    float v1 = acc[mt][nt][half * 2 + 1] + f1bias[bt * 96 + ncol + 1];
                    v0 = 0.5f * v0 * (1.f + erff(v0 * 0.70710678118654752f));
                    v1 = 0.5f * v1 * (1.f + erff(v1 * 0.70710678118654752f));
                    *(uint32_t*)&g_m1[row * 384 + bt * 96 + ncol] = packbf(v0, v1);
                }
            }
    }
}

// ============================================================
// K5: fc2 GEMM (K=384, 4 chunks) + residual + transpose to out
// ============================================================
__global__ void __launch_bounds__(256)
k_fc2(const float* __restrict__ f2bias, float* __restrict__ out)
{
    extern __shared__ char smem[];
    uint32_t* As = (uint32_t*)smem;
    uint32_t* Bs = (uint32_t*)(smem + 26624);
    float* sout  = (float*)smem;     // 48*132, reuse after mainloop

    int tid = threadIdx.x;
    size_t bm = (size_t)blockIdx.x * 128;
    int warp = tid >> 5, lane = tid & 31, g = lane >> 2, t4 = lane & 3;
    int wm = warp >> 1, wn = warp & 1;

    float acc[2][6][4];
    #pragma unroll
    for (int i = 0; i < 2; i++)
        #pragma unroll
        for (int j = 0; j < 6; j++)
            #pragma unroll
            for (int r = 0; r < 4; r++) acc[i][j][r] = 0.f;

    for (int kc = 0; kc < 4; kc++) {
        if (kc) __syncthreads();
        int k0 = kc * 96;
        for (int i = tid; i < 128 * 12; i += 256) {
            int row = i / 12, q = i - row * 12;
            ((uint4*)&As[row * PITCH])[q] = ((const uint4*)(g_m1 + (bm + row) * 384 + k0))[q];
        }
        for (int i = tid; i < 96 * 12; i += 256) {
            int row = i / 12, q = i - row * 12;
            ((uint4*)&Bs[row * PITCH])[q] = ((const uint4*)(g_wfc2 + (size_t)row * 384 + k0))[q];
        }
        __syncthreads();
        mma_tile96(As, Bs, acc, g, t4, wm, wn);
    }
    __syncthreads();

    int b   = (int)(bm >> 17);
    int sp0 = (int)(bm & (SP - 1));

    #pragma unroll
    for (int p = 0; p < 2; p++) {
        if (wn == p) {
            #pragma unroll
            for (int mt = 0; mt < 2; mt++)
                #pragma unroll
                for (int nt = 0; nt < 6; nt++) {
                    int cl = nt * 8 + t4 * 2;
                    #pragma unroll
                    for (int half = 0; half < 2; half++) {
                        int rl = wm * 32 + mt * 16 + g + half * 8;
                        float2 xv = *(const float2*)&g_x2[(bm + rl) * 96 + p * 48 + cl];
                        sout[(cl    ) * 132 + rl] = acc[mt][nt][half * 2 + 0] + f2bias[p * 48 + cl    ] + xv.x;
                        sout[(cl + 1) * 132 + rl] = acc[mt][nt][half * 2 + 1] + f2bias[p * 48 + cl + 1] + xv.y;
                    }
                }
        }
        __syncthreads();
        for (int i = tid; i < 48 * 128; i += 256) {
            int c = i >> 7, tk = i & 127;
            out[((size_t)b * 96 + p * 48 + c) * SP + sp0 + tk] = sout[c * 132 + tk];
        }
        __syncthreads();
    }
}

// ============================================================
// launch
// ============================================================
extern "C" void kernel_launch(void* const* d_in, const int* in_sizes, int n_in,
                              void* d_out, int out_size)
{
    const float* x    = (const float*)d_in[0];
    const float* n1g  = (const float*)d_in[1];
    const float* n1b  = (const float*)d_in[2];
    const float* qkvw = (const float*)d_in[3];
    const float* qkvb = (const float*)d_in[4];
    const float* rpb  = (const float*)d_in[5];
    const float* pw   = (const float*)d_in[6];
    const float* pb   = (const float*)d_in[7];
    const float* n2g  = (const float*)d_in[8];
    const float* n2b  = (const float*)d_in[9];
    const float* f1w  = (const float*)d_in[10];
    const float* f1b  = (const float*)d_in[11];
    const float* f2w  = (const float*)d_in[12];
    const float* f2b  = (const float*)d_in[13];
    float* out = (float*)d_out;

    static int smem_set = 0;
    if (!smem_set) {
        cudaFuncSetAttribute(k_qkv,  cudaFuncAttributeMaxDynamicSharedMemorySize, 48 * 1024);
        cudaFuncSetAttribute(k_attn, cudaFuncAttributeMaxDynamicSharedMemorySize, 56 * 1024);
        cudaFuncSetAttribute(k_proj, cudaFuncAttributeMaxDynamicSharedMemorySize, 52 * 1024);
        cudaFuncSetAttribute(k_fc1,  cudaFuncAttributeMaxDynamicSharedMemorySize, 47 * 1024);
        cudaFuncSetAttribute(k_fc2,  cudaFuncAttributeMaxDynamicSharedMemorySize, 47 * 1024);
        smem_set = 1;
    }

    const int SZ_QKV  = 46592 + 768;
    const int SZ_ATTN = 4 * 64 * 24 * 4 * 2 + 4 * 344 * 4 + 64 * 4;  // 55104
    const int SZ_PROJ = 51968;
    const int SZ_GEMM = 46592;

    k_wconv<<<432, 256>>>(qkvw, pw, f1w, f2w);
    k_qkv <<<NTOK / 128, 256, SZ_QKV >>>(x, n1g, n1b, qkvb);
    k_attn<<<BATCH * NWIN, 256, SZ_ATTN>>>(rpb);
    k_proj<<<NTOK / 128, 256, SZ_PROJ>>>(x, pb, n2g, n2b);
    k_fc1 <<<NTOK / 128, 256, SZ_GEMM>>>(f1b);
    k_fc2 <<<NTOK / 128, 256, SZ_GEMM>>>(f2b, out);
}